// round 7
// baseline (speedup 1.0000x reference)
#include <cuda_runtime.h>
#include <cuda_bf16.h>

// HintGenKernelBatched: masked XOR-parity gather-reduce.
//   entries:        [1000000, 5]  int32
//   padded_indices: [4096, 2048]  int32 in [0, 1e6)
//   valid_mask:     [4096, 2048]  int32 in {0, 1}
//   out:            [4096, 5]     float32 (numeric convert; values < 2^31)
//
// R6 profile: L1 66% top, issue 49%, L2 45% -> mixed latency/L1 bound; ~27%
// of L1 wavefronts were per-row broadcast LDS + 4x loop bookkeeping.
// This version: each 8-lane group pulls FOUR row indices with one LDS.128
// (int4) and issues 4 predicated cooperative gathers back-to-back.
//   - LDS wavefronts /4, phase-2 instructions /1.8, 4-deep gather MLP.

#define MAX_SUBSET 2048
#define ROW 5
#define THREADS 256
#define NGROUPS (THREADS / 8)                   // 32 row-gather groups per CTA
#define NITER (MAX_SUBSET / 4 / NGROUPS)        // 16 int4-iterations per group

__global__ __launch_bounds__(THREADS, 8) void hint_parity_kernel(
    const int* __restrict__ entries,
    const int* __restrict__ padded_indices,
    const int* __restrict__ valid_mask,
    float* __restrict__ out)
{
    __shared__ int4 sidx4[MAX_SUBSET / 4];      // masked indices, -1 = invalid
    __shared__ unsigned red[THREADS / 32][ROW];

    const int h = blockIdx.x;
    const int t = threadIdx.x;
    const size_t base = (size_t)h * MAX_SUBSET;

    const int4* __restrict__ idx4 = reinterpret_cast<const int4*>(padded_indices + base);
    const int4* __restrict__ msk4 = reinterpret_cast<const int4*>(valid_mask + base);

    // ---- Phase 1: coalesced stream + mask fold into smem ----
    #pragma unroll
    for (int p = 0; p < MAX_SUBSET / (THREADS * 4); ++p) {
        const int4 iv = idx4[p * THREADS + t];
        const int4 mv = msk4[p * THREADS + t];
        int4 o;
        o.x = mv.x ? iv.x : -1;
        o.y = mv.y ? iv.y : -1;
        o.z = mv.z ? iv.z : -1;
        o.w = mv.w ? iv.w : -1;
        sidx4[p * THREADS + t] = o;             // STS.128, conflict-free
    }
    __syncthreads();

    // ---- Phase 2: cooperative gather, one 8-lane group per row,
    //      4 rows per LDS.128 of indices ----
    const int lane = t & 31;
    const int warp = t >> 5;
    const int g    = t >> 3;                    // group id 0..31
    const int j    = t & 7;                     // word-within-row (j<5 active)
    const bool wlane = (j < ROW);

    unsigned acc = 0;

    #pragma unroll
    for (int p = 0; p < NITER; ++p) {
        const int4 q = sidx4[p * NGROUPS + g];  // LDS.128 broadcast within group

        if (wlane) {
            if (q.x >= 0) acc ^= (unsigned)__ldg(entries + (size_t)(unsigned)q.x * ROW + j);
            if (q.y >= 0) acc ^= (unsigned)__ldg(entries + (size_t)(unsigned)q.y * ROW + j);
            if (q.z >= 0) acc ^= (unsigned)__ldg(entries + (size_t)(unsigned)q.z * ROW + j);
            if (q.w >= 0) acc ^= (unsigned)__ldg(entries + (size_t)(unsigned)q.w * ROW + j);
        }
    }

    // ---- Reduce the 4 groups of each warp (lanes with equal t&7 combine) ----
    acc ^= __shfl_xor_sync(0xffffffffu, acc, 8);
    acc ^= __shfl_xor_sync(0xffffffffu, acc, 16);

    // lanes 0..4 of each warp now hold the warp's parity for words 0..4
    if (lane < ROW) red[warp][lane] = acc;
    __syncthreads();

    // ---- Fold 8 warps, store float32 ----
    if (t < ROW) {
        unsigned v = red[0][t];
        #pragma unroll
        for (int w = 1; w < THREADS / 32; ++w) v ^= red[w][t];
        out[(size_t)h * ROW + t] = (float)v;    // numeric convert, values < 2^31
    }
}

extern "C" void kernel_launch(void* const* d_in, const int* in_sizes, int n_in,
                              void* d_out, int out_size)
{
    const int* entries        = (const int*)d_in[0];
    const int* padded_indices = (const int*)d_in[1];
    const int* valid_mask     = (const int*)d_in[2];
    float* out = (float*)d_out;

    const int num_hints = out_size / ROW;  // 4096
    hint_parity_kernel<<<num_hints, THREADS>>>(entries, padded_indices, valid_mask, out);
}